// round 1
// baseline (speedup 1.0000x reference)
#include <cuda_runtime.h>
#include <cuda_bf16.h>
#include <cstdint>

// Problem constants
#define NTOK   8192      // B*S
#define DIM    1024
#define NEXP   8
#define LN_EPS 1e-5f

// GEMM tiling
#define MT 64
#define NT 128
#define KT 32

// ---------------- scratch (device globals; no allocation allowed) -----------
__device__ int   d_cnt[NEXP];
__device__ int   d_tok[NEXP * NTOK];
__device__ float d_wt [NEXP * NTOK];

// ---------------- helpers ---------------------------------------------------
__device__ __forceinline__ uint32_t f2tf32(float f) {
    uint32_t u;
    asm volatile("cvt.rna.tf32.f32 %0, %1;" : "=r"(u) : "f"(f));
    return u;
}

__device__ __forceinline__ void mma_tf32(float c[4], const uint32_t a[4], const uint32_t b[2]) {
    asm volatile(
        "mma.sync.aligned.m16n8k8.row.col.f32.tf32.tf32.f32 "
        "{%0,%1,%2,%3}, {%4,%5,%6,%7}, {%8,%9}, {%0,%1,%2,%3};\n"
        : "+f"(c[0]), "+f"(c[1]), "+f"(c[2]), "+f"(c[3])
        : "r"(a[0]), "r"(a[1]), "r"(a[2]), "r"(a[3]),
          "r"(b[0]), "r"(b[1]));
}

// ---------------- kernel 0: zero output + counters ---------------------------
__global__ void zero_kernel(float* __restrict__ out) {
    size_t i = (size_t)blockIdx.x * blockDim.x + threadIdx.x;
    ((float4*)out)[i] = make_float4(0.f, 0.f, 0.f, 0.f);
    if (blockIdx.x == 0 && threadIdx.x < NEXP) d_cnt[threadIdx.x] = 0;
}

// ---------------- kernel 1: routing + scatter --------------------------------
// one warp per token
__global__ void routing_kernel(const float* __restrict__ x,
                               const float* __restrict__ noise,
                               const float* __restrict__ Wr,
                               const float* __restrict__ br,
                               const float* __restrict__ gamma,
                               const float* __restrict__ beta) {
    int warp = threadIdx.x >> 5;
    int lane = threadIdx.x & 31;
    int t = blockIdx.x * 8 + warp;

    float acc[8] = {0.f,0.f,0.f,0.f,0.f,0.f,0.f,0.f};
    const float* xrow = x + (size_t)t * DIM;

    #pragma unroll 4
    for (int i = 0; i < DIM / 32; i++) {
        int d = i * 32 + lane;
        float xv = xrow[d];
        const float4* wp = (const float4*)&Wr[d * 8];
        float4 w0 = wp[0];
        float4 w1 = wp[1];
        acc[0] += xv * w0.x; acc[1] += xv * w0.y;
        acc[2] += xv * w0.z; acc[3] += xv * w0.w;
        acc[4] += xv * w1.x; acc[5] += xv * w1.y;
        acc[6] += xv * w1.z; acc[7] += xv * w1.w;
    }
    #pragma unroll
    for (int off = 16; off; off >>= 1) {
        #pragma unroll
        for (int e = 0; e < 8; e++)
            acc[e] += __shfl_down_sync(0xffffffffu, acc[e], off);
    }

    if (lane == 0) {
        float l[8];
        float mu = 0.f;
        #pragma unroll
        for (int e = 0; e < 8; e++) { l[e] = acc[e] + br[e]; mu += l[e]; }
        mu *= (1.f / 8.f);
        float var = 0.f;
        #pragma unroll
        for (int e = 0; e < 8; e++) { float d = l[e] - mu; var += d * d; }
        var *= (1.f / 8.f);
        float rstd = rsqrtf(var + LN_EPS);
        float mx = -1e30f;
        #pragma unroll
        for (int e = 0; e < 8; e++) {
            l[e] = (l[e] - mu) * rstd * gamma[e] + beta[e];
            mx = fmaxf(mx, l[e]);
        }
        float s = 0.f, p[8];
        #pragma unroll
        for (int e = 0; e < 8; e++) { p[e] = __expf(0.f) * expf(l[e] - mx); s += p[e]; }
        float inv = 1.f / s;
        float r[8];
        #pragma unroll
        for (int e = 0; e < 8; e++) r[e] = p[e] * inv + noise[t * 8 + e];

        // top-2, ties -> lowest index first (matches jax.lax.top_k)
        int i0 = 0; float v0 = r[0];
        #pragma unroll
        for (int e = 1; e < 8; e++) if (r[e] > v0) { v0 = r[e]; i0 = e; }
        int i1 = -1; float v1 = -1e30f;
        #pragma unroll
        for (int e = 0; e < 8; e++) if (e != i0 && r[e] > v1) { v1 = r[e]; i1 = e; }

        float e1 = expf(v1 - v0);
        float w0 = 1.f / (1.f + e1);
        float w1 = e1 / (1.f + e1);

        int p0 = atomicAdd(&d_cnt[i0], 1);
        d_tok[i0 * NTOK + p0] = t; d_wt[i0 * NTOK + p0] = w0;
        int p1 = atomicAdd(&d_cnt[i1], 1);
        d_tok[i1 * NTOK + p1] = t; d_wt[i1 * NTOK + p1] = w1;
    }
}

// ---------------- kernel 2: grouped expert GEMM (tf32 mma.sync) ---------------
// grid: (DIM/NT, NTOK/MT, NEXP), 256 threads
__global__ __launch_bounds__(256) void moe_gemm(const float* __restrict__ x,
                                                const float* __restrict__ Wexp,
                                                const float* __restrict__ bexp,
                                                float* __restrict__ out) {
    const int e     = blockIdx.z;
    const int mtile = blockIdx.y;
    const int ntile = blockIdx.x;
    const int cnt   = d_cnt[e];
    const int row0  = mtile * MT;
    if (row0 >= cnt) return;

    __shared__ uint32_t As[MT][36];    // padded: bank = (4*row + col) % 32, conflict-free frags
    __shared__ uint32_t Bs[KT][132];
    __shared__ int   stok[MT];
    __shared__ float swt[MT];

    const int tid  = threadIdx.x;
    const int warp = tid >> 5;
    const int lane = tid & 31;
    const int wm   = warp & 1;   // 0..1  (M direction, 32 rows each)
    const int wn   = warp >> 1;  // 0..3  (N direction, 32 cols each)
    const int gid  = lane >> 2;
    const int tg   = lane & 3;
    const int n0   = ntile * NT;

    if (tid < MT) {
        int r = row0 + tid;
        bool ok = (r < cnt);
        stok[tid] = ok ? d_tok[e * NTOK + r] : -1;
        swt[tid]  = ok ? d_wt [e * NTOK + r] : 0.f;
    }
    __syncthreads();

    float acc[2][4][4];
    #pragma unroll
    for (int mi = 0; mi < 2; mi++)
        #pragma unroll
        for (int ni = 0; ni < 4; ni++)
            #pragma unroll
            for (int q = 0; q < 4; q++) acc[mi][ni][q] = 0.f;

    for (int k0 = 0; k0 < DIM; k0 += KT) {
        // load A (gathered token rows): 64 x 32 floats
        {
            int c4 = (tid & 7) * 4;
            #pragma unroll
            for (int rr = 0; rr < 2; rr++) {
                int r = (tid >> 3) + rr * 32;
                int tok = stok[r];
                float4 v = (tok >= 0)
                    ? *(const float4*)&x[(size_t)tok * DIM + k0 + c4]
                    : make_float4(0.f, 0.f, 0.f, 0.f);
                As[r][c4 + 0] = f2tf32(v.x);
                As[r][c4 + 1] = f2tf32(v.y);
                As[r][c4 + 2] = f2tf32(v.z);
                As[r][c4 + 3] = f2tf32(v.w);
            }
        }
        // load B = W_exp[e][k0..k0+32][n0..n0+128]
        {
            int c4 = (tid & 31) * 4;
            #pragma unroll
            for (int rr = 0; rr < 4; rr++) {
                int r = (tid >> 5) + rr * 8;
                const float4 v = *(const float4*)&Wexp[((size_t)e * DIM + (k0 + r)) * DIM + n0 + c4];
                Bs[r][c4 + 0] = f2tf32(v.x);
                Bs[r][c4 + 1] = f2tf32(v.y);
                Bs[r][c4 + 2] = f2tf32(v.z);
                Bs[r][c4 + 3] = f2tf32(v.w);
            }
        }
        __syncthreads();

        #pragma unroll
        for (int kk = 0; kk < KT; kk += 8) {
            uint32_t a[2][4], b[4][2];
            #pragma unroll
            for (int mi = 0; mi < 2; mi++) {
                int rb = wm * 32 + mi * 16;
                a[mi][0] = As[rb + gid    ][kk + tg];
                a[mi][1] = As[rb + gid + 8][kk + tg];
                a[mi][2] = As[rb + gid    ][kk + tg + 4];
                a[mi][3] = As[rb + gid + 8][kk + tg + 4];
            }
            #pragma unroll
            for (int ni = 0; ni < 4; ni++) {
                int cb = wn * 32 + ni * 8;
                b[ni][0] = Bs[kk + tg    ][cb + gid];
                b[ni][1] = Bs[kk + tg + 4][cb + gid];
            }
            #pragma unroll
            for (int mi = 0; mi < 2; mi++)
                #pragma unroll
                for (int ni = 0; ni < 4; ni++)
                    mma_tf32(acc[mi][ni], a[mi], b[ni]);
        }
        __syncthreads();
    }

    // epilogue: out[tok] += w * (acc + bias)
    #pragma unroll
    for (int mi = 0; mi < 2; mi++) {
        #pragma unroll
        for (int half = 0; half < 2; half++) {
            int r = wm * 32 + mi * 16 + half * 8 + gid;
            int tok = stok[r];
            if (tok < 0) continue;
            float w = swt[r];
            float* orow = out + (size_t)tok * DIM;
            #pragma unroll
            for (int ni = 0; ni < 4; ni++) {
                int col = n0 + wn * 32 + ni * 8 + tg * 2;
                float c0 = acc[mi][ni][half * 2 + 0];
                float c1 = acc[mi][ni][half * 2 + 1];
                atomicAdd(&orow[col],     w * (c0 + bexp[e * DIM + col]));
                atomicAdd(&orow[col + 1], w * (c1 + bexp[e * DIM + col + 1]));
            }
        }
    }
}

// ---------------- launch ------------------------------------------------------
extern "C" void kernel_launch(void* const* d_in, const int* in_sizes, int n_in,
                              void* d_out, int out_size) {
    const float* x     = (const float*)d_in[0];
    const float* noise = (const float*)d_in[1];
    const float* Wr    = (const float*)d_in[2];
    const float* br    = (const float*)d_in[3];
    const float* gamma = (const float*)d_in[4];
    const float* beta  = (const float*)d_in[5];
    const float* Wexp  = (const float*)d_in[6];
    const float* bexp  = (const float*)d_in[7];
    float* out = (float*)d_out;

    // zero out (NTOK*DIM floats = 2,097,152 float4) + counters
    zero_kernel<<<(NTOK * DIM / 4) / 256, 256>>>(out);
    // routing: one warp per token
    routing_kernel<<<NTOK / 8, 256>>>(x, noise, Wr, br, gamma, beta);
    // grouped expert GEMM
    moe_gemm<<<dim3(DIM / NT, NTOK / MT, NEXP), 256>>>(x, Wexp, bexp, out);
}

// round 3
// speedup vs baseline: 1.5466x; 1.5466x over previous
#include <cuda_runtime.h>
#include <cuda_bf16.h>
#include <cstdint>

// Problem constants
#define NTOK   8192      // B*S
#define DIM    1024
#define NEXP   8
#define LN_EPS 1e-5f

// GEMM tiling
#define MT 128
#define NT 128
#define KT 32
#define ASTRIDE 36   // padded floats per A row
#define BSTRIDE 132  // padded floats per B row

#define SMEM_BYTES (2*MT*ASTRIDE*4 + 2*KT*BSTRIDE*4 + MT*4 + MT*4)

// ---------------- scratch (device globals; no allocation allowed) -----------
__device__ int   d_cnt[NEXP];
__device__ int   d_tok[NEXP * NTOK];
__device__ float d_wt [NEXP * NTOK];

// ---------------- helpers ---------------------------------------------------
__device__ __forceinline__ uint32_t f2tf32(float f) {
    uint32_t u;
    asm volatile("cvt.rna.tf32.f32 %0, %1;" : "=r"(u) : "f"(f));
    return u;
}

__device__ __forceinline__ void mma_tf32(float c[4], const uint32_t a[4], const uint32_t b[2]) {
    asm volatile(
        "mma.sync.aligned.m16n8k8.row.col.f32.tf32.tf32.f32 "
        "{%0,%1,%2,%3}, {%4,%5,%6,%7}, {%8,%9}, {%0,%1,%2,%3};\n"
        : "+f"(c[0]), "+f"(c[1]), "+f"(c[2]), "+f"(c[3])
        : "r"(a[0]), "r"(a[1]), "r"(a[2]), "r"(a[3]),
          "r"(b[0]), "r"(b[1]));
}

__device__ __forceinline__ void cp16(uint32_t dst, const void* src) {
    asm volatile("cp.async.cg.shared.global [%0], [%1], 16;" :: "r"(dst), "l"(src));
}
__device__ __forceinline__ void cp_commit() {
    asm volatile("cp.async.commit_group;");
}
__device__ __forceinline__ void cp_wait1() {
    asm volatile("cp.async.wait_group 1;");
}
__device__ __forceinline__ void red_v2(float* p, float v0, float v1) {
    asm volatile("red.global.add.v2.f32 [%0], {%1, %2};" :: "l"(p), "f"(v0), "f"(v1) : "memory");
}

// ---------------- kernel 0: zero output + counters ---------------------------
__global__ void zero_kernel(float* __restrict__ out) {
    size_t i = (size_t)blockIdx.x * blockDim.x + threadIdx.x;
    ((float4*)out)[i] = make_float4(0.f, 0.f, 0.f, 0.f);
    if (blockIdx.x == 0 && threadIdx.x < NEXP) d_cnt[threadIdx.x] = 0;
}

// ---------------- kernel 1: routing + scatter --------------------------------
// one warp per token
__global__ void routing_kernel(const float* __restrict__ x,
                               const float* __restrict__ noise,
                               const float* __restrict__ Wr,
                               const float* __restrict__ br,
                               const float* __restrict__ gamma,
                               const float* __restrict__ beta) {
    int warp = threadIdx.x >> 5;
    int lane = threadIdx.x & 31;
    int t = blockIdx.x * 8 + warp;

    float acc[8] = {0.f,0.f,0.f,0.f,0.f,0.f,0.f,0.f};
    const float* xrow = x + (size_t)t * DIM;

    #pragma unroll 4
    for (int i = 0; i < DIM / 32; i++) {
        int d = i * 32 + lane;
        float xv = xrow[d];
        const float4* wp = (const float4*)&Wr[d * 8];
        float4 w0 = wp[0];
        float4 w1 = wp[1];
        acc[0] += xv * w0.x; acc[1] += xv * w0.y;
        acc[2] += xv * w0.z; acc[3] += xv * w0.w;
        acc[4] += xv * w1.x; acc[5] += xv * w1.y;
        acc[6] += xv * w1.z; acc[7] += xv * w1.w;
    }
    #pragma unroll
    for (int off = 16; off; off >>= 1) {
        #pragma unroll
        for (int e = 0; e < 8; e++)
            acc[e] += __shfl_down_sync(0xffffffffu, acc[e], off);
    }

    if (lane == 0) {
        float l[8];
        float mu = 0.f;
        #pragma unroll
        for (int e = 0; e < 8; e++) { l[e] = acc[e] + br[e]; mu += l[e]; }
        mu *= (1.f / 8.f);
        float var = 0.f;
        #pragma unroll
        for (int e = 0; e < 8; e++) { float d = l[e] - mu; var += d * d; }
        var *= (1.f / 8.f);
        float rstd = rsqrtf(var + LN_EPS);
        float mx = -1e30f;
        #pragma unroll
        for (int e = 0; e < 8; e++) {
            l[e] = (l[e] - mu) * rstd * gamma[e] + beta[e];
            mx = fmaxf(mx, l[e]);
        }
        float s = 0.f, p[8];
        #pragma unroll
        for (int e = 0; e < 8; e++) { p[e] = expf(l[e] - mx); s += p[e]; }
        float inv = 1.f / s;
        float r[8];
        #pragma unroll
        for (int e = 0; e < 8; e++) r[e] = p[e] * inv + noise[t * 8 + e];

        // top-2, ties -> lowest index first (matches jax.lax.top_k)
        int i0 = 0; float v0 = r[0];
        #pragma unroll
        for (int e = 1; e < 8; e++) if (r[e] > v0) { v0 = r[e]; i0 = e; }
        int i1 = -1; float v1 = -1e30f;
        #pragma unroll
        for (int e = 0; e < 8; e++) if (e != i0 && r[e] > v1) { v1 = r[e]; i1 = e; }

        float e1 = expf(v1 - v0);
        float w0 = 1.f / (1.f + e1);
        float w1 = e1 / (1.f + e1);

        int p0 = atomicAdd(&d_cnt[i0], 1);
        d_tok[i0 * NTOK + p0] = t; d_wt[i0 * NTOK + p0] = w0;
        int p1 = atomicAdd(&d_cnt[i1], 1);
        d_tok[i1 * NTOK + p1] = t; d_wt[i1 * NTOK + p1] = w1;
    }
}

// ---------------- kernel 2: grouped expert GEMM (tf32 mma.sync, cp.async x2) --
// grid: (DIM/NT, 64, NEXP), 256 threads
__global__ __launch_bounds__(256) void moe_gemm(const float* __restrict__ x,
                                                const float* __restrict__ Wexp,
                                                const float* __restrict__ bexp,
                                                float* __restrict__ out) {
    const int e     = blockIdx.z;
    const int mtile = blockIdx.y;
    const int ntile = blockIdx.x;
    const int cnt   = d_cnt[e];
    const int row0  = mtile * MT;
    if (row0 >= cnt) return;

    extern __shared__ char smem_raw[];
    float* As   = (float*)smem_raw;                    // [2][MT][ASTRIDE]
    float* Bs   = As + 2 * MT * ASTRIDE;               // [2][KT][BSTRIDE]
    int*   stok = (int*)(Bs + 2 * KT * BSTRIDE);       // [MT]
    float* swt  = (float*)(stok + MT);                 // [MT]

    const int tid  = threadIdx.x;
    const int warp = tid >> 5;
    const int lane = tid & 31;
    const int wm   = warp & 1;   // 0..1  (M direction, 64 rows each)
    const int wn   = warp >> 1;  // 0..3  (N direction, 32 cols each)
    const int gid  = lane >> 2;
    const int tg   = lane & 3;
    const int n0   = ntile * NT;

    if (tid < MT) {
        int r = row0 + tid;
        bool ok = (r < cnt);
        stok[tid] = ok ? d_tok[e * NTOK + r] : -1;
        swt[tid]  = ok ? d_wt [e * NTOK + r] : 0.f;
    }
    __syncthreads();

    // per-thread load coordinates
    const int arow = tid >> 3;          // 0..31 (rows arow + 32j)
    const int acol = (tid & 7) * 4;     // float4 col
    const int brow = tid >> 5;          // 0..7 (rows brow + 8j)
    const int bcol = (tid & 31) * 4;

    uint32_t as_base = (uint32_t)__cvta_generic_to_shared(As);
    uint32_t bs_base = (uint32_t)__cvta_generic_to_shared(Bs);

    auto load_stage = [&](int s, int k0) {
        #pragma unroll
        for (int j = 0; j < 4; j++) {
            int r = arow + j * 32;
            int tok = stok[r];
            uint32_t dst = as_base + ((s * MT + r) * ASTRIDE + acol) * 4;
            if (tok >= 0)
                cp16(dst, &x[(size_t)tok * DIM + k0 + acol]);
            else
                *(float4*)(As + (s * MT + r) * ASTRIDE + acol) = make_float4(0.f,0.f,0.f,0.f);
        }
        #pragma unroll
        for (int j = 0; j < 4; j++) {
            int r = brow + j * 8;
            uint32_t dst = bs_base + ((s * KT + r) * BSTRIDE + bcol) * 4;
            cp16(dst, &Wexp[((size_t)e * DIM + (k0 + r)) * DIM + n0 + bcol]);
        }
    };

    float acc[4][4][4];
    #pragma unroll
    for (int mi = 0; mi < 4; mi++)
        #pragma unroll
        for (int ni = 0; ni < 4; ni++)
            #pragma unroll
            for (int q = 0; q < 4; q++) acc[mi][ni][q] = 0.f;

    // pipeline prologue
    load_stage(0, 0);
    cp_commit();

    const int NKT = DIM / KT;  // 32
    for (int kt = 0; kt < NKT; kt++) {
        if (kt + 1 < NKT) load_stage((kt + 1) & 1, (kt + 1) * KT);
        cp_commit();
        cp_wait1();
        __syncthreads();

        const int s = kt & 1;
        const float* Asl = As + s * MT * ASTRIDE;
        const float* Bsl = Bs + s * KT * BSTRIDE;
        #pragma unroll
        for (int kk = 0; kk < KT; kk += 8) {
            uint32_t a[4][4], b[4][2];
            #pragma unroll
            for (int mi = 0; mi < 4; mi++) {
                int rb = wm * 64 + mi * 16;
                a[mi][0] = f2tf32(Asl[(rb + gid    ) * ASTRIDE + kk + tg]);
                a[mi][1] = f2tf32(Asl[(rb + gid + 8) * ASTRIDE + kk + tg]);
                a[mi][2] = f2tf32(Asl[(rb + gid    ) * ASTRIDE + kk + tg + 4]);
                a[mi][3] = f2tf32(Asl[(rb + gid + 8) * ASTRIDE + kk + tg + 4]);
            }
            #pragma unroll
            for (int ni = 0; ni < 4; ni++) {
                int cb = wn * 32 + ni * 8;
                b[ni][0] = f2tf32(Bsl[(kk + tg    ) * BSTRIDE + cb + gid]);
                b[ni][1] = f2tf32(Bsl[(kk + tg + 4) * BSTRIDE + cb + gid]);
            }
            #pragma unroll
            for (int mi = 0; mi < 4; mi++)
                #pragma unroll
                for (int ni = 0; ni < 4; ni++)
                    mma_tf32(acc[mi][ni], a[mi], b[ni]);
        }
        __syncthreads();
    }

    // epilogue: out[tok] += w * (acc + bias), vectorized red.v2
    #pragma unroll
    for (int mi = 0; mi < 4; mi++) {
        #pragma unroll
        for (int half = 0; half < 2; half++) {
            int r = wm * 64 + mi * 16 + half * 8 + gid;
            int tok = stok[r];
            if (tok < 0) continue;
            float w = swt[r];
            float* orow = out + (size_t)tok * DIM;
            #pragma unroll
            for (int ni = 0; ni < 4; ni++) {
                int col = n0 + wn * 32 + ni * 8 + tg * 2;
                float2 bb = *(const float2*)&bexp[e * DIM + col];
                float v0 = w * (acc[mi][ni][half * 2 + 0] + bb.x);
                float v1 = w * (acc[mi][ni][half * 2 + 1] + bb.y);
                red_v2(&orow[col], v0, v1);
            }
        }
    }
}

// ---------------- launch ------------------------------------------------------
extern "C" void kernel_launch(void* const* d_in, const int* in_sizes, int n_in,
                              void* d_out, int out_size) {
    const float* x     = (const float*)d_in[0];
    const float* noise = (const float*)d_in[1];
    const float* Wr    = (const float*)d_in[2];
    const float* br    = (const float*)d_in[3];
    const float* gamma = (const float*)d_in[4];
    const float* beta  = (const float*)d_in[5];
    const float* Wexp  = (const float*)d_in[6];
    const float* bexp  = (const float*)d_in[7];
    float* out = (float*)d_out;

    cudaFuncSetAttribute(moe_gemm, cudaFuncAttributeMaxDynamicSharedMemorySize, SMEM_BYTES);

    // zero out (NTOK*DIM floats) + counters
    zero_kernel<<<(NTOK * DIM / 4) / 256, 256>>>(out);
    // routing: one warp per token
    routing_kernel<<<NTOK / 8, 256>>>(x, noise, Wr, br, gamma, beta);
    // grouped expert GEMM (max 64 m-tiles per expert; blocks early-exit)
    moe_gemm<<<dim3(DIM / NT, NTOK / MT, NEXP), 256, SMEM_BYTES>>>(x, Wexp, bexp, out);
}

// round 5
// speedup vs baseline: 1.6167x; 1.0453x over previous
#include <cuda_runtime.h>
#include <cuda_bf16.h>
#include <cstdint>

// Problem constants
#define NTOK   8192      // B*S
#define DIM    1024
#define NEXP   8
#define LN_EPS 1e-5f

// GEMM tiling
#define MT 128
#define NT 128
#define KT 16
#define NSTAGE 3
#define ASTR 20    // padded floats per A row (16 + 4)
#define BSTR 136   // padded floats per B row (128 + 8): row-bank offset = 8 mod 32

#define SMEM_BYTES (NSTAGE*MT*ASTR*4 + NSTAGE*KT*BSTR*4 + MT*4 + MT*4)

// ---------------- scratch (device globals; no allocation allowed) -----------
__device__ int   d_cnt[NEXP];
__device__ int   d_tok[NEXP * NTOK];
__device__ float d_wt [NEXP * NTOK];

// ---------------- helpers ---------------------------------------------------
__device__ __forceinline__ uint32_t f2tf32(float f) {
    uint32_t u;
    asm volatile("cvt.rna.tf32.f32 %0, %1;" : "=r"(u) : "f"(f));
    return u;
}

__device__ __forceinline__ void mma_tf32(float c[4], const uint32_t a[4], const uint32_t b[2]) {
    asm volatile(
        "mma.sync.aligned.m16n8k8.row.col.f32.tf32.tf32.f32 "
        "{%0,%1,%2,%3}, {%4,%5,%6,%7}, {%8,%9}, {%0,%1,%2,%3};\n"
        : "+f"(c[0]), "+f"(c[1]), "+f"(c[2]), "+f"(c[3])
        : "r"(a[0]), "r"(a[1]), "r"(a[2]), "r"(a[3]),
          "r"(b[0]), "r"(b[1]));
}

__device__ __forceinline__ void cp16(uint32_t dst, const void* src) {
    asm volatile("cp.async.cg.shared.global [%0], [%1], 16;" :: "r"(dst), "l"(src));
}
__device__ __forceinline__ void cp_commit() {
    asm volatile("cp.async.commit_group;");
}
__device__ __forceinline__ void cp_wait1() {
    asm volatile("cp.async.wait_group 1;");
}
__device__ __forceinline__ void red_v2(float* p, float v0, float v1) {
    asm volatile("red.global.add.v2.f32 [%0], {%1, %2};" :: "l"(p), "f"(v0), "f"(v1) : "memory");
}

// ---------------- kernel 0: zero output + counters ---------------------------
__global__ void zero_kernel(float* __restrict__ out) {
    size_t i = (size_t)blockIdx.x * blockDim.x + threadIdx.x;
    ((float4*)out)[i] = make_float4(0.f, 0.f, 0.f, 0.f);
    if (blockIdx.x == 0 && threadIdx.x < NEXP) d_cnt[threadIdx.x] = 0;
}

// ---------------- kernel 1: routing + scatter --------------------------------
// one warp per token
__global__ void routing_kernel(const float* __restrict__ x,
                               const float* __restrict__ noise,
                               const float* __restrict__ Wr,
                               const float* __restrict__ br,
                               const float* __restrict__ gamma,
                               const float* __restrict__ beta) {
    int warp = threadIdx.x >> 5;
    int lane = threadIdx.x & 31;
    int t = blockIdx.x * 8 + warp;

    float acc[8] = {0.f,0.f,0.f,0.f,0.f,0.f,0.f,0.f};
    const float* xrow = x + (size_t)t * DIM;

    #pragma unroll 4
    for (int i = 0; i < DIM / 32; i++) {
        int d = i * 32 + lane;
        float xv = xrow[d];
        const float4* wp = (const float4*)&Wr[d * 8];
        float4 w0 = wp[0];
        float4 w1 = wp[1];
        acc[0] += xv * w0.x; acc[1] += xv * w0.y;
        acc[2] += xv * w0.z; acc[3] += xv * w0.w;
        acc[4] += xv * w1.x; acc[5] += xv * w1.y;
        acc[6] += xv * w1.z; acc[7] += xv * w1.w;
    }
    #pragma unroll
    for (int off = 16; off; off >>= 1) {
        #pragma unroll
        for (int e = 0; e < 8; e++)
            acc[e] += __shfl_down_sync(0xffffffffu, acc[e], off);
    }

    if (lane == 0) {
        float l[8];
        float mu = 0.f;
        #pragma unroll
        for (int e = 0; e < 8; e++) { l[e] = acc[e] + br[e]; mu += l[e]; }
        mu *= (1.f / 8.f);
        float var = 0.f;
        #pragma unroll
        for (int e = 0; e < 8; e++) { float d = l[e] - mu; var += d * d; }
        var *= (1.f / 8.f);
        float rstd = rsqrtf(var + LN_EPS);
        float mx = -1e30f;
        #pragma unroll
        for (int e = 0; e < 8; e++) {
            l[e] = (l[e] - mu) * rstd * gamma[e] + beta[e];
            mx = fmaxf(mx, l[e]);
        }
        float s = 0.f, p[8];
        #pragma unroll
        for (int e = 0; e < 8; e++) { p[e] = expf(l[e] - mx); s += p[e]; }
        float inv = 1.f / s;
        float r[8];
        #pragma unroll
        for (int e = 0; e < 8; e++) r[e] = p[e] * inv + noise[t * 8 + e];

        // top-2, ties -> lowest index first (matches jax.lax.top_k)
        int i0 = 0; float v0 = r[0];
        #pragma unroll
        for (int e = 1; e < 8; e++) if (r[e] > v0) { v0 = r[e]; i0 = e; }
        int i1 = -1; float v1 = -1e30f;
        #pragma unroll
        for (int e = 0; e < 8; e++) if (e != i0 && r[e] > v1) { v1 = r[e]; i1 = e; }

        float e1 = expf(v1 - v0);
        float w0 = 1.f / (1.f + e1);
        float w1 = e1 / (1.f + e1);

        int p0 = atomicAdd(&d_cnt[i0], 1);
        d_tok[i0 * NTOK + p0] = t; d_wt[i0 * NTOK + p0] = w0;
        int p1 = atomicAdd(&d_cnt[i1], 1);
        d_tok[i1 * NTOK + p1] = t; d_wt[i1 * NTOK + p1] = w1;
    }
}

// ---------------- kernel 2: grouped expert GEMM (tf32 mma.sync, 3-stage) ------
// grid: (DIM/NT, NTOK/MT, NEXP), 256 threads
__global__ __launch_bounds__(256, 2) void moe_gemm(const float* __restrict__ x,
                                                   const float* __restrict__ Wexp,
                                                   const float* __restrict__ bexp,
                                                   float* __restrict__ out) {
    const int e     = blockIdx.z;
    const int mtile = blockIdx.y;
    const int ntile = blockIdx.x;
    const int cnt   = d_cnt[e];
    const int row0  = mtile * MT;
    if (row0 >= cnt) return;

    extern __shared__ char smem_raw[];
    float* As   = (float*)smem_raw;                       // [NSTAGE][MT][ASTR]
    float* Bs   = As + NSTAGE * MT * ASTR;                // [NSTAGE][KT][BSTR]
    int*   stok = (int*)(Bs + NSTAGE * KT * BSTR);        // [MT]
    float* swt  = (float*)(stok + MT);                    // [MT]

    const int tid  = threadIdx.x;
    const int warp = tid >> 5;
    const int lane = tid & 31;
    const int wm   = warp & 1;   // 0..1  (M direction, 64 rows each)
    const int wn   = warp >> 1;  // 0..3  (N direction, 32 cols each)
    const int gid  = lane >> 2;
    const int tg   = lane & 3;
    const int n0   = ntile * NT;

    if (tid < MT) {
        int r = row0 + tid;
        bool ok = (r < cnt);
        stok[tid] = ok ? d_tok[e * NTOK + r] : -1;
        swt[tid]  = ok ? d_wt [e * NTOK + r] : 0.f;
    }
    __syncthreads();

    // per-thread load coordinates
    const int arow = tid >> 2;          // 0..63 (rows arow, arow+64)
    const int acol = (tid & 3) * 4;     // float4 col within 16
    const int brow = tid >> 5;          // 0..7 (rows brow, brow+8)
    const int bcol = (tid & 31) * 4;

    uint32_t as_base = (uint32_t)__cvta_generic_to_shared(As);
    uint32_t bs_base = (uint32_t)__cvta_generic_to_shared(Bs);

    auto load_stage = [&](int s, int k0) {
        #pragma unroll
        for (int j = 0; j < 2; j++) {
            int r = arow + j * 64;
            int tok = stok[r];
            uint32_t dst = as_base + ((s * MT + r) * ASTR + acol) * 4;
            if (tok >= 0)
                cp16(dst, &x[(size_t)tok * DIM + k0 + acol]);
            else
                *(float4*)(As + (s * MT + r) * ASTR + acol) = make_float4(0.f,0.f,0.f,0.f);
        }
        #pragma unroll
        for (int j = 0; j < 2; j++) {
            int r = brow + j * 8;
            uint32_t dst = bs_base + ((s * KT + r) * BSTR + bcol) * 4;
            cp16(dst, &Wexp[((size_t)e * DIM + (k0 + r)) * DIM + n0 + bcol]);
        }
    };

    float acc[4][4][4];
    #pragma unroll
    for (int mi = 0; mi < 4; mi++)
        #pragma unroll
        for (int ni = 0; ni < 4; ni++)
            #pragma unroll
            for (int q = 0; q < 4; q++) acc[mi][ni][q] = 0.f;

    // pipeline prologue: stages 0,1 in flight
    load_stage(0, 0);       cp_commit();
    load_stage(1, KT);      cp_commit();

    const int NKT = DIM / KT;  // 64
    int cs = 0;                // compute stage = kt % NSTAGE
    for (int kt = 0; kt < NKT; kt++) {
        cp_wait1();            // group kt complete (group kt+1 may be pending)
        __syncthreads();       // all warps done with stage (kt-1): safe to refill

        // issue loads for kt+2 into stage (kt+2)%3 == (kt-1)%3
        int ls = cs + 2; if (ls >= NSTAGE) ls -= NSTAGE;
        if (kt + 2 < NKT) load_stage(ls, (kt + 2) * KT);
        cp_commit();           // keep group numbering consistent even when empty

        const float* Asl = As + cs * MT * ASTR;
        const float* Bsl = Bs + cs * KT * BSTR;
        #pragma unroll
        for (int kk = 0; kk < KT; kk += 8) {
            uint32_t a[4][4], b[4][2];
            #pragma unroll
            for (int mi = 0; mi < 4; mi++) {
                int rb = wm * 64 + mi * 16;
                a[mi][0] = f2tf32(Asl[(rb + gid    ) * ASTR + kk + tg]);
                a[mi][1] = f2tf32(Asl[(rb + gid + 8) * ASTR + kk + tg]);
                a[mi][2] = f2tf32(Asl[(rb + gid    ) * ASTR + kk + tg + 4]);
                a[mi][3] = f2tf32(Asl[(rb + gid + 8) * ASTR + kk + tg + 4]);
            }
            #pragma unroll
            for (int ni = 0; ni < 4; ni++) {
                int cb = wn * 32 + ni * 8;
                b[ni][0] = f2tf32(Bsl[(kk + tg    ) * BSTR + cb + gid]);
                b[ni][1] = f2tf32(Bsl[(kk + tg + 4) * BSTR + cb + gid]);
            }
            #pragma unroll
            for (int mi = 0; mi < 4; mi++)
                #pragma unroll
                for (int ni = 0; ni < 4; ni++)
                    mma_tf32(acc[mi][ni], a[mi], b[ni]);
        }

        cs++; if (cs >= NSTAGE) cs = 0;
    }

    // epilogue: out[tok] += w * (acc + bias), vectorized red.v2
    #pragma unroll
    for (int mi = 0; mi < 4; mi++) {
        #pragma unroll
        for (int half = 0; half < 2; half++) {
            int r = wm * 64 + mi * 16 + half * 8 + gid;
            int tok = stok[r];
            if (tok < 0) continue;
            float w = swt[r];
            float* orow = out + (size_t)tok * DIM;
            #pragma unroll
            for (int ni = 0; ni < 4; ni++) {
                int col = n0 + wn * 32 + ni * 8 + tg * 2;
                float2 bb = *(const float2*)&bexp[e * DIM + col];
                float v0 = w * (acc[mi][ni][half * 2 + 0] + bb.x);
                float v1 = w * (acc[mi][ni][half * 2 + 1] + bb.y);
                red_v2(&orow[col], v0, v1);
            }
        }
    }
}

// ---------------- launch ------------------------------------------------------
extern "C" void kernel_launch(void* const* d_in, const int* in_sizes, int n_in,
                              void* d_out, int out_size) {
    const float* x     = (const float*)d_in[0];
    const float* noise = (const float*)d_in[1];
    const float* Wr    = (const float*)d_in[2];
    const float* br    = (const float*)d_in[3];
    const float* gamma = (const float*)d_in[4];
    const float* beta  = (const float*)d_in[5];
    const float* Wexp  = (const float*)d_in[6];
    const float* bexp  = (const float*)d_in[7];
    float* out = (float*)d_out;

    cudaFuncSetAttribute(moe_gemm, cudaFuncAttributeMaxDynamicSharedMemorySize, SMEM_BYTES);

    // zero out (NTOK*DIM floats) + counters
    zero_kernel<<<(NTOK * DIM / 4) / 256, 256>>>(out);
    // routing: one warp per token
    routing_kernel<<<NTOK / 8, 256>>>(x, noise, Wr, br, gamma, beta);
    // grouped expert GEMM (blocks past each expert's count early-exit)
    moe_gemm<<<dim3(DIM / NT, NTOK / MT, NEXP), 256, SMEM_BYTES>>>(x, Wexp, bexp, out);
}

// round 8
// speedup vs baseline: 1.9673x; 1.2168x over previous
#include <cuda_runtime.h>
#include <cuda_fp16.h>
#include <cstdint>

// Problem constants
#define NTOK   8192      // B*S
#define DIM    1024
#define NEXP   8
#define LN_EPS 1e-5f

// GEMM tiling (fp16 mma.sync m16n8k16)
#define MT 128
#define NT 128
#define KT 32
#define NSTAGE 3
#define ASTR 40    // padded halfs per A row (32 + 8) -> 80B row stride
#define BSTR 40    // padded halfs per B row (k-major) -> 80B

#define SMEM_BYTES (NSTAGE*MT*ASTR*2 + NSTAGE*NT*BSTR*2 + MT*4 + MT*4)

// ---------------- scratch (device globals; no allocation allowed) -----------
__device__ int    d_cnt[NEXP];
__device__ int    d_tok[NEXP * NTOK];
__device__ float  d_wt [NEXP * NTOK];
__device__ __half d_xh [NTOK * DIM];            // x in fp16
__device__ __half d_wh [NEXP * DIM * DIM];      // W_exp transposed: [e][n][k] fp16

// ---------------- helpers ---------------------------------------------------
__device__ __forceinline__ void mma_f16(float c[4], const uint32_t a[4], const uint32_t b[2]) {
    asm volatile(
        "mma.sync.aligned.m16n8k16.row.col.f32.f16.f16.f32 "
        "{%0,%1,%2,%3}, {%4,%5,%6,%7}, {%8,%9}, {%0,%1,%2,%3};\n"
        : "+f"(c[0]), "+f"(c[1]), "+f"(c[2]), "+f"(c[3])
        : "r"(a[0]), "r"(a[1]), "r"(a[2]), "r"(a[3]),
          "r"(b[0]), "r"(b[1]));
}
__device__ __forceinline__ void cp16(uint32_t dst, const void* src) {
    asm volatile("cp.async.cg.shared.global [%0], [%1], 16;" :: "r"(dst), "l"(src));
}
__device__ __forceinline__ void cp_commit() { asm volatile("cp.async.commit_group;"); }
__device__ __forceinline__ void cp_wait1()  { asm volatile("cp.async.wait_group 1;"); }
__device__ __forceinline__ void red_v2(float* p, float v0, float v1) {
    asm volatile("red.global.add.v2.f32 [%0], {%1, %2};" :: "l"(p), "f"(v0), "f"(v1) : "memory");
}

// ---------------- kernel 0: zero output + counters ---------------------------
__global__ void zero_kernel(float* __restrict__ out) {
    size_t i = (size_t)blockIdx.x * blockDim.x + threadIdx.x;
    ((float4*)out)[i] = make_float4(0.f, 0.f, 0.f, 0.f);
    if (blockIdx.x == 0 && threadIdx.x < NEXP) d_cnt[threadIdx.x] = 0;
}

// ---------------- kernel 0b: convert x -> fp16 -------------------------------
__global__ void convert_x(const float* __restrict__ x) {
    size_t i = (size_t)blockIdx.x * blockDim.x + threadIdx.x;   // 8 elems per thread
    const float4* src = (const float4*)x;
    float4 v0 = src[i * 2 + 0];
    float4 v1 = src[i * 2 + 1];
    __half2 h[4];
    h[0] = __floats2half2_rn(v0.x, v0.y);
    h[1] = __floats2half2_rn(v0.z, v0.w);
    h[2] = __floats2half2_rn(v1.x, v1.y);
    h[3] = __floats2half2_rn(v1.z, v1.w);
    ((uint4*)d_xh)[i] = *(uint4*)h;
}

// ---------------- kernel 0c: convert + transpose W_exp -> fp16 [e][n][k] -----
__global__ void convert_w(const float* __restrict__ W) {
    __shared__ __half t[32][33];
    int e  = blockIdx.z;
    int n0 = blockIdx.x * 32;
    int k0 = blockIdx.y * 32;
    int tx = threadIdx.x, ty = threadIdx.y;   // 32 x 8
    #pragma unroll
    for (int j = 0; j < 32; j += 8)
        t[ty + j][tx] = __float2half(W[((size_t)e * DIM + k0 + ty + j) * DIM + n0 + tx]);
    __syncthreads();
    #pragma unroll
    for (int j = 0; j < 32; j += 8)
        d_wh[((size_t)e * DIM + n0 + ty + j) * DIM + k0 + tx] = t[tx][ty + j];
}

// ---------------- kernel 1: routing + scatter --------------------------------
// one warp per token
__global__ void routing_kernel(const float* __restrict__ x,
                               const float* __restrict__ noise,
                               const float* __restrict__ Wr,
                               const float* __restrict__ br,
                               const float* __restrict__ gamma,
                               const float* __restrict__ beta) {
    int warp = threadIdx.x >> 5;
    int lane = threadIdx.x & 31;
    int t = blockIdx.x * 8 + warp;

    float acc[8] = {0.f,0.f,0.f,0.f,0.f,0.f,0.f,0.f};
    const float* xrow = x + (size_t)t * DIM;

    #pragma unroll 4
    for (int i = 0; i < DIM / 32; i++) {
        int d = i * 32 + lane;
        float xv = xrow[d];
        const float4* wp = (const float4*)&Wr[d * 8];
        float4 w0 = wp[0];
        float4 w1 = wp[1];
        acc[0] += xv * w0.x; acc[1] += xv * w0.y;
        acc[2] += xv * w0.z; acc[3] += xv * w0.w;
        acc[4] += xv * w1.x; acc[5] += xv * w1.y;
        acc[6] += xv * w1.z; acc[7] += xv * w1.w;
    }
    #pragma unroll
    for (int off = 16; off; off >>= 1) {
        #pragma unroll
        for (int e = 0; e < 8; e++)
            acc[e] += __shfl_down_sync(0xffffffffu, acc[e], off);
    }

    if (lane == 0) {
        float l[8];
        float mu = 0.f;
        #pragma unroll
        for (int e = 0; e < 8; e++) { l[e] = acc[e] + br[e]; mu += l[e]; }
        mu *= (1.f / 8.f);
        float var = 0.f;
        #pragma unroll
        for (int e = 0; e < 8; e++) { float d = l[e] - mu; var += d * d; }
        var *= (1.f / 8.f);
        float rstd = rsqrtf(var + LN_EPS);
        float mx = -1e30f;
        #pragma unroll
        for (int e = 0; e < 8; e++) {
            l[e] = (l[e] - mu) * rstd * gamma[e] + beta[e];
            mx = fmaxf(mx, l[e]);
        }
        float s = 0.f, p[8];
        #pragma unroll
        for (int e = 0; e < 8; e++) { p[e] = expf(l[e] - mx); s += p[e]; }
        float inv = 1.f / s;
        float r[8];
        #pragma unroll
        for (int e = 0; e < 8; e++) r[e] = p[e] * inv + noise[t * 8 + e];

        // top-2, ties -> lowest index first (matches jax.lax.top_k)
        int i0 = 0; float v0 = r[0];
        #pragma unroll
        for (int e = 1; e < 8; e++) if (r[e] > v0) { v0 = r[e]; i0 = e; }
        int i1 = -1; float v1 = -1e30f;
        #pragma unroll
        for (int e = 0; e < 8; e++) if (e != i0 && r[e] > v1) { v1 = r[e]; i1 = e; }

        float e1 = expf(v1 - v0);
        float w0 = 1.f / (1.f + e1);
        float w1 = e1 / (1.f + e1);

        int p0 = atomicAdd(&d_cnt[i0], 1);
        d_tok[i0 * NTOK + p0] = t; d_wt[i0 * NTOK + p0] = w0;
        int p1 = atomicAdd(&d_cnt[i1], 1);
        d_tok[i1 * NTOK + p1] = t; d_wt[i1 * NTOK + p1] = w1;
    }
}

// ---------------- kernel 2: grouped expert GEMM (fp16 mma.sync, 3-stage) ------
// grid: (DIM/NT, NTOK/MT, NEXP), 256 threads
// A smem: [MT][ASTR] halfs (m-major, k contiguous)
// B smem: [NT][BSTR] halfs (n-major, k contiguous)  <- pre-transposed weights
__global__ __launch_bounds__(256, 2) void moe_gemm(const float* __restrict__ bexp,
                                                   float* __restrict__ out) {
    const int e     = blockIdx.z;
    const int mtile = blockIdx.y;
    const int ntile = blockIdx.x;
    const int cnt   = d_cnt[e];
    const int row0  = mtile * MT;
    if (row0 >= cnt) return;

    extern __shared__ char smem_raw[];
    __half* As  = (__half*)smem_raw;                      // [NSTAGE][MT][ASTR]
    __half* Bs  = As + NSTAGE * MT * ASTR;                // [NSTAGE][NT][BSTR]
    int*   stok = (int*)(Bs + NSTAGE * NT * BSTR);        // [MT]
    float* swt  = (float*)(stok + MT);                    // [MT]

    const int tid  = threadIdx.x;
    const int warp = tid >> 5;
    const int lane = tid & 31;
    const int wm   = warp & 1;   // 0..1  (M direction, 64 rows each)
    const int wn   = warp >> 1;  // 0..3  (N direction, 32 cols each)
    const int gid  = lane >> 2;
    const int tg   = lane & 3;
    const int n0   = ntile * NT;

    if (tid < MT) {
        int r = row0 + tid;
        bool ok = (r < cnt);
        stok[tid] = ok ? d_tok[e * NTOK + r] : -1;
        swt[tid]  = ok ? d_wt [e * NTOK + r] : 0.f;
    }
    __syncthreads();

    uint32_t as_base = (uint32_t)__cvta_generic_to_shared(As);
    uint32_t bs_base = (uint32_t)__cvta_generic_to_shared(Bs);

    // loaders: 128 rows x 4 chunks(16B) each for A and B; 256 threads -> 2 chunks each
    const int r_a = tid >> 1;                 // rows r_a, r_a+... wait: 128 rows, 2 chunk-cols per thread
    auto load_stage = [&](int s, int k0) {
        // A: row = tid>>1, chunks (tid&1) and (tid&1)+2
        {
            int row = tid >> 1;
            int tok = stok[row];
            const __half* src = d_xh + (size_t)tok * DIM + k0;
            #pragma unroll
            for (int j = 0; j < 2; j++) {
                int c16 = (tid & 1) + j * 2;          // 16B chunk index 0..3
                uint32_t dst = as_base + (uint32_t)(((s * MT + row) * ASTR + c16 * 8) * 2);
                if (tok >= 0) cp16(dst, src + c16 * 8);
                else {
                    asm volatile("st.shared.v4.b32 [%0], {%1,%1,%1,%1};" :: "r"(dst), "r"(0u));
                }
            }
        }
        // B: row(n) = tid>>1, chunks along k
        {
            int row = tid >> 1;
            const __half* src = d_wh + ((size_t)e * DIM + n0 + row) * DIM + k0;
            #pragma unroll
            for (int j = 0; j < 2; j++) {
                int c16 = (tid & 1) + j * 2;
                uint32_t dst = bs_base + (uint32_t)(((s * NT + row) * BSTR + c16 * 8) * 2);
                cp16(dst, src + c16 * 8);
            }
        }
    };

    float acc[4][4][4];
    #pragma unroll
    for (int mi = 0; mi < 4; mi++)
        #pragma unroll
        for (int ni = 0; ni < 4; ni++)
            #pragma unroll
            for (int q = 0; q < 4; q++) acc[mi][ni][q] = 0.f;

    // pipeline prologue: stages 0,1 in flight
    load_stage(0, 0);      cp_commit();
    load_stage(1, KT);     cp_commit();

    const int NKT = DIM / KT;  // 32
    int cs = 0;
    for (int kt = 0; kt < NKT; kt++) {
        cp_wait1();
        __syncthreads();

        int ls = cs + 2; if (ls >= NSTAGE) ls -= NSTAGE;
        if (kt + 2 < NKT) load_stage(ls, (kt + 2) * KT);
        cp_commit();

        const __half* Asl = As + cs * MT * ASTR;
        const __half* Bsl = Bs + cs * NT * BSTR;
        #pragma unroll
        for (int kk = 0; kk < KT; kk += 16) {
            uint32_t a[4][4], b[4][2];
            #pragma unroll
            for (int mi = 0; mi < 4; mi++) {
                int rb = wm * 64 + mi * 16;
                a[mi][0] = *(const uint32_t*)&Asl[(rb + gid    ) * ASTR + kk + 2 * tg];
                a[mi][1] = *(const uint32_t*)&Asl[(rb + gid + 8) * ASTR + kk + 2 * tg];
                a[mi][2] = *(const uint32_t*)&Asl[(rb + gid    ) * ASTR + kk + 2 * tg + 8];
                a[mi][3] = *(const uint32_t*)&Asl[(rb + gid + 8) * ASTR + kk + 2 * tg + 8];
            }
            #pragma unroll
            for (int ni = 0; ni < 4; ni++) {
                int cb = wn * 32 + ni * 8 + gid;
                b[ni][0] = *(const uint32_t*)&Bsl[cb * BSTR + kk + 2 * tg];
                b[ni][1] = *(const uint32_t*)&Bsl[cb * BSTR + kk + 2 * tg + 8];
            }
            #pragma unroll
            for (int mi = 0; mi < 4; mi++)
                #pragma unroll
                for (int ni = 0; ni < 4; ni++)
                    mma_f16(acc[mi][ni], a[mi], b[ni]);
        }

        cs++; if (cs >= NSTAGE) cs = 0;
    }

    // epilogue: out[tok] += w * (acc + bias), vectorized red.v2
    #pragma unroll
    for (int mi = 0; mi < 4; mi++) {
        #pragma unroll
        for (int half = 0; half < 2; half++) {
            int r = wm * 64 + mi * 16 + half * 8 + gid;
            int tok = stok[r];
            if (tok < 0) continue;
            float w = swt[r];
            float* orow = out + (size_t)tok * DIM;
            #pragma unroll
            for (int ni = 0; ni < 4; ni++) {
                int col = n0 + wn * 32 + ni * 8 + tg * 2;
                float2 bb = *(const float2*)&bexp[e * DIM + col];
                float v0 = w * (acc[mi][ni][half * 2 + 0] + bb.x);
                float v1 = w * (acc[mi][ni][half * 2 + 1] + bb.y);
                red_v2(&orow[col], v0, v1);
            }
        }
    }
}

// ---------------- launch ------------------------------------------------------
extern "C" void kernel_launch(void* const* d_in, const int* in_sizes, int n_in,
                              void* d_out, int out_size) {
    const float* x     = (const float*)d_in[0];
    const float* noise = (const float*)d_in[1];
    const float* Wr    = (const float*)d_in[2];
    const float* br    = (const float*)d_in[3];
    const float* gamma = (const float*)d_in[4];
    const float* beta  = (const float*)d_in[5];
    const float* Wexp  = (const float*)d_in[6];
    const float* bexp  = (const float*)d_in[7];
    float* out = (float*)d_out;

    cudaFuncSetAttribute(moe_gemm, cudaFuncAttributeMaxDynamicSharedMemorySize, SMEM_BYTES);

    zero_kernel<<<(NTOK * DIM / 4) / 256, 256>>>(out);
    convert_x<<<(NTOK * DIM / 8) / 256, 256>>>(x);
    convert_w<<<dim3(DIM / 32, DIM / 32, NEXP), dim3(32, 8)>>>(Wexp);
    routing_kernel<<<NTOK / 8, 256>>>(x, noise, Wr, br, gamma, beta);
    moe_gemm<<<dim3(DIM / NT, NTOK / MT, NEXP), 256, SMEM_BYTES>>>(bexp, out);
}

// round 11
// speedup vs baseline: 2.0007x; 1.0170x over previous
#include <cuda_runtime.h>
#include <cuda_fp16.h>
#include <cstdint>

// Problem constants
#define NTOK   8192      // B*S
#define DIM    1024
#define NEXP   8
#define LN_EPS 1e-5f

// GEMM tiling (fp16 mma.sync m16n8k16)
#define MT 128
#define NT 128
#define KT 32
#define NSTAGE 3
#define ASTR 40    // padded halfs per A row -> 80B stride
#define BSTR 40

#define SMEM_BYTES (NSTAGE*MT*ASTR*2 + NSTAGE*NT*BSTR*2 + MT*4 + MT*4)

// ---------------- scratch (device globals; no allocation allowed) -----------
__device__ int    d_cnt[NEXP];
__device__ int    d_tok[NEXP * NTOK];       // packed tok*2 + slot
__device__ float  d_wt [NEXP * NTOK];
__device__ __half d_xh [NTOK * DIM];        // x fp16 (emitted by routing)
__device__ __half d_wh [NEXP * DIM * DIM];  // W_exp transposed [e][n][k] fp16
__device__ float  d_scr[2 * NTOK * DIM];    // per-slot expert outputs

// ---------------- helpers ---------------------------------------------------
__device__ __forceinline__ void mma_f16(float c[4], const uint32_t a[4], const uint32_t b[2]) {
    asm volatile(
        "mma.sync.aligned.m16n8k16.row.col.f32.f16.f16.f32 "
        "{%0,%1,%2,%3}, {%4,%5,%6,%7}, {%8,%9}, {%0,%1,%2,%3};\n"
        : "+f"(c[0]), "+f"(c[1]), "+f"(c[2]), "+f"(c[3])
        : "r"(a[0]), "r"(a[1]), "r"(a[2]), "r"(a[3]),
          "r"(b[0]), "r"(b[1]));
}
__device__ __forceinline__ void cp16(uint32_t dst, const void* src) {
    asm volatile("cp.async.cg.shared.global [%0], [%1], 16;" :: "r"(dst), "l"(src));
}
__device__ __forceinline__ void cp_commit() { asm volatile("cp.async.commit_group;"); }
__device__ __forceinline__ void cp_wait1()  { asm volatile("cp.async.wait_group 1;"); }

// ---------------- kernel: init counters --------------------------------------
__global__ void init_kernel() {
    if (threadIdx.x < NEXP) d_cnt[threadIdx.x] = 0;
}

// ---------------- kernel: convert + transpose W_exp -> fp16 [e][n][k] --------
__global__ void convert_w(const float* __restrict__ W) {
    __shared__ __half t[32][33];
    int e  = blockIdx.z;
    int n0 = blockIdx.x * 32;
    int k0 = blockIdx.y * 32;
    int tx = threadIdx.x, ty = threadIdx.y;   // 32 x 8
    #pragma unroll
    for (int j = 0; j < 32; j += 8)
        t[ty + j][tx] = __float2half(W[((size_t)e * DIM + k0 + ty + j) * DIM + n0 + tx]);
    __syncthreads();
    #pragma unroll
    for (int j = 0; j < 32; j += 8)
        d_wh[((size_t)e * DIM + n0 + ty + j) * DIM + k0 + tx] = t[tx][ty + j];
}

// ---------------- kernel: routing (+ fp16 x emit) -----------------------------
// one warp per token, 8 warps/block; W_route transposed in smem
__global__ __launch_bounds__(256) void routing_kernel(const float* __restrict__ x,
                                                      const float* __restrict__ noise,
                                                      const float* __restrict__ Wr,
                                                      const float* __restrict__ br,
                                                      const float* __restrict__ gamma,
                                                      const float* __restrict__ beta) {
    __shared__ float sW[8][1024];
    const int tid  = threadIdx.x;
    const int warp = tid >> 5;
    const int lane = tid & 31;

    // load + transpose W_route [1024][8] -> sW[e][d]
    const float4* w4 = (const float4*)Wr;
    for (int j = tid; j < 2048; j += 256) {
        float4 v = w4[j];
        int idx = j * 4;
        int d  = idx >> 3;
        int e0 = idx & 7;
        sW[e0 + 0][d] = v.x;
        sW[e0 + 1][d] = v.y;
        sW[e0 + 2][d] = v.z;
        sW[e0 + 3][d] = v.w;
    }
    __syncthreads();

    const int t = blockIdx.x * 8 + warp;
    const float4* xr = (const float4*)(x + (size_t)t * DIM);
    __half* xh = d_xh + (size_t)t * DIM;

    float acc[8] = {0.f,0.f,0.f,0.f,0.f,0.f,0.f,0.f};
    #pragma unroll
    for (int i = 0; i < 8; i++) {
        float4 xv = xr[i * 32 + lane];
        int d = i * 128 + lane * 4;
        #pragma unroll
        for (int e = 0; e < 8; e++) {
            float4 wv = *(const float4*)&sW[e][d];
            acc[e] += xv.x * wv.x + xv.y * wv.y + xv.z * wv.z + xv.w * wv.w;
        }
        __half2 h0 = __floats2half2_rn(xv.x, xv.y);
        __half2 h1 = __floats2half2_rn(xv.z, xv.w);
        *(__half2*)&xh[d + 0] = h0;
        *(__half2*)&xh[d + 2] = h1;
    }
    #pragma unroll
    for (int off = 16; off; off >>= 1) {
        #pragma unroll
        for (int e = 0; e < 8; e++)
            acc[e] += __shfl_down_sync(0xffffffffu, acc[e], off);
    }

    if (lane == 0) {
        float l[8];
        float mu = 0.f;
        #pragma unroll
        for (int e = 0; e < 8; e++) { l[e] = acc[e] + br[e]; mu += l[e]; }
        mu *= (1.f / 8.f);
        float var = 0.f;
        #pragma unroll
        for (int e = 0; e < 8; e++) { float d = l[e] - mu; var += d * d; }
        var *= (1.f / 8.f);
        float rstd = rsqrtf(var + LN_EPS);
        float mx = -1e30f;
        #pragma unroll
        for (int e = 0; e < 8; e++) {
            l[e] = (l[e] - mu) * rstd * gamma[e] + beta[e];
            mx = fmaxf(mx, l[e]);
        }
        float s = 0.f, p[8];
        #pragma unroll
        for (int e = 0; e < 8; e++) { p[e] = expf(l[e] - mx); s += p[e]; }
        float inv = 1.f / s;
        float r[8];
        #pragma unroll
        for (int e = 0; e < 8; e++) r[e] = p[e] * inv + noise[t * 8 + e];

        // top-2, ties -> lowest index (jax.lax.top_k)
        int i0 = 0; float v0 = r[0];
        #pragma unroll
        for (int e = 1; e < 8; e++) if (r[e] > v0) { v0 = r[e]; i0 = e; }
        int i1 = -1; float v1 = -1e30f;
        #pragma unroll
        for (int e = 0; e < 8; e++) if (e != i0 && r[e] > v1) { v1 = r[e]; i1 = e; }

        float e1 = expf(v1 - v0);
        float w0 = 1.f / (1.f + e1);
        float w1 = e1 / (1.f + e1);

        int p0 = atomicAdd(&d_cnt[i0], 1);
        d_tok[i0 * NTOK + p0] = t * 2 + 0; d_wt[i0 * NTOK + p0] = w0;
        int p1 = atomicAdd(&d_cnt[i1], 1);
        d_tok[i1 * NTOK + p1] = t * 2 + 1; d_wt[i1 * NTOK + p1] = w1;
    }
}

// ---------------- kernel: grouped expert GEMM (fp16 mma.sync, 3-stage) --------
// grid: (DIM/NT, NTOK/MT, NEXP), 256 threads
__global__ __launch_bounds__(256, 2) void moe_gemm(const float* __restrict__ bexp) {
    const int e     = blockIdx.z;
    const int mtile = blockIdx.y;
    const int ntile = blockIdx.x;
    const int cnt   = d_cnt[e];
    const int row0  = mtile * MT;
    if (row0 >= cnt) return;

    extern __shared__ char smem_raw[];
    __half* As  = (__half*)smem_raw;                      // [NSTAGE][MT][ASTR]
    __half* Bs  = As + NSTAGE * MT * ASTR;                // [NSTAGE][NT][BSTR]
    int*   stok = (int*)(Bs + NSTAGE * NT * BSTR);        // [MT]
    float* swt  = (float*)(stok + MT);                    // [MT]

    const int tid  = threadIdx.x;
    const int warp = tid >> 5;
    const int lane = tid & 31;
    const int wm   = warp & 1;   // 0..1  (M direction, 64 rows each)
    const int wn   = warp >> 1;  // 0..3  (N direction, 32 cols each)
    const int gid  = lane >> 2;
    const int tg   = lane & 3;
    const int n0   = ntile * NT;

    if (tid < MT) {
        int r = row0 + tid;
        bool ok = (r < cnt);
        stok[tid] = ok ? d_tok[e * NTOK + r] : -1;
        swt[tid]  = ok ? d_wt [e * NTOK + r] : 0.f;
    }
    __syncthreads();

    uint32_t as_base = (uint32_t)__cvta_generic_to_shared(As);
    uint32_t bs_base = (uint32_t)__cvta_generic_to_shared(Bs);

    auto load_stage = [&](int s, int k0) {
        // A: row = tid>>1, chunks (tid&1), (tid&1)+2
        {
            int row = tid >> 1;
            int tok2 = stok[row];
            const __half* src = d_xh + (size_t)(tok2 >> 1) * DIM + k0;
            #pragma unroll
            for (int j = 0; j < 2; j++) {
                int c16 = (tid & 1) + j * 2;
                uint32_t dst = as_base + (uint32_t)(((s * MT + row) * ASTR + c16 * 8) * 2);
                if (tok2 >= 0) cp16(dst, src + c16 * 8);
                else asm volatile("st.shared.v4.b32 [%0], {%1,%1,%1,%1};" :: "r"(dst), "r"(0u));
            }
        }
        // B: n-row = tid>>1, chunks along k
        {
            int row = tid >> 1;
            const __half* src = d_wh + ((size_t)e * DIM + n0 + row) * DIM + k0;
            #pragma unroll
            for (int j = 0; j < 2; j++) {
                int c16 = (tid & 1) + j * 2;
                uint32_t dst = bs_base + (uint32_t)(((s * NT + row) * BSTR + c16 * 8) * 2);
                cp16(dst, src + c16 * 8);
            }
        }
    };

    float acc[4][4][4];
    #pragma unroll
    for (int mi = 0; mi < 4; mi++)
        #pragma unroll
        for (int ni = 0; ni < 4; ni++)
            #pragma unroll
            for (int q = 0; q < 4; q++) acc[mi][ni][q] = 0.f;

    load_stage(0, 0);      cp_commit();
    load_stage(1, KT);     cp_commit();

    const int NKT = DIM / KT;  // 32
    int cs = 0;
    for (int kt = 0; kt < NKT; kt++) {
        cp_wait1();
        __syncthreads();

        int ls = cs + 2; if (ls >= NSTAGE) ls -= NSTAGE;
        if (kt + 2 < NKT) load_stage(ls, (kt + 2) * KT);
        cp_commit();

        const __half* Asl = As + cs * MT * ASTR;
        const __half* Bsl = Bs + cs * NT * BSTR;
        #pragma unroll
        for (int kk = 0; kk < KT; kk += 16) {
            uint32_t a[4][4], b[4][2];
            #pragma unroll
            for (int mi = 0; mi < 4; mi++) {
                int rb = wm * 64 + mi * 16;
                a[mi][0] = *(const uint32_t*)&Asl[(rb + gid    ) * ASTR + kk + 2 * tg];
                a[mi][1] = *(const uint32_t*)&Asl[(rb + gid + 8) * ASTR + kk + 2 * tg];
                a[mi][2] = *(const uint32_t*)&Asl[(rb + gid    ) * ASTR + kk + 2 * tg + 8];
                a[mi][3] = *(const uint32_t*)&Asl[(rb + gid + 8) * ASTR + kk + 2 * tg + 8];
            }
            #pragma unroll
            for (int ni = 0; ni < 4; ni++) {
                int cb = wn * 32 + ni * 8 + gid;
                b[ni][0] = *(const uint32_t*)&Bsl[cb * BSTR + kk + 2 * tg];
                b[ni][1] = *(const uint32_t*)&Bsl[cb * BSTR + kk + 2 * tg + 8];
            }
            #pragma unroll
            for (int mi = 0; mi < 4; mi++)
                #pragma unroll
                for (int ni = 0; ni < 4; ni++)
                    mma_f16(acc[mi][ni], a[mi], b[ni]);
        }

        cs++; if (cs >= NSTAGE) cs = 0;
    }

    // epilogue: d_scr[slot][tok] = w * (acc + bias)   (pure STG, no atomics)
    #pragma unroll
    for (int mi = 0; mi < 4; mi++) {
        #pragma unroll
        for (int half = 0; half < 2; half++) {
            int r = wm * 64 + mi * 16 + half * 8 + gid;
            int tok2 = stok[r];
            if (tok2 < 0) continue;
            float w = swt[r];
            float* orow = d_scr + ((size_t)(tok2 & 1) * NTOK + (size_t)(tok2 >> 1)) * DIM;
            #pragma unroll
            for (int ni = 0; ni < 4; ni++) {
                int col = n0 + wn * 32 + ni * 8 + tg * 2;
                float2 bb = *(const float2*)&bexp[e * DIM + col];
                float2 v;
                v.x = w * (acc[mi][ni][half * 2 + 0] + bb.x);
                v.y = w * (acc[mi][ni][half * 2 + 1] + bb.y);
                *(float2*)&orow[col] = v;
            }
        }
    }
}

// ---------------- kernel: combine two slots ----------------------------------
__global__ void combine_kernel(float* __restrict__ out) {
    size_t i = (size_t)blockIdx.x * blockDim.x + threadIdx.x;
    const float4* s0 = (const float4*)d_scr;
    const float4* s1 = (const float4*)(d_scr + (size_t)NTOK * DIM);
    float4 a = s0[i], b = s1[i];
    ((float4*)out)[i] = make_float4(a.x + b.x, a.y + b.y, a.z + b.z, a.w + b.w);
}

// ---------------- launch ------------------------------------------------------
extern "C" void kernel_launch(void* const* d_in, const int* in_sizes, int n_in,
                              void* d_out, int out_size) {
    const float* x     = (const float*)d_in[0];
    const float* noise = (const float*)d_in[1];
    const float* Wr    = (const float*)d_in[2];
    const float* br    = (const float*)d_in[3];
    const float* gamma = (const float*)d_in[4];
    const float* beta  = (const float*)d_in[5];
    const float* Wexp  = (const float*)d_in[6];
    const float* bexp  = (const float*)d_in[7];
    float* out = (float*)d_out;

    cudaFuncSetAttribute(moe_gemm, cudaFuncAttributeMaxDynamicSharedMemorySize, SMEM_BYTES);

    init_kernel<<<1, 32>>>();
    convert_w<<<dim3(DIM / 32, DIM / 32, NEXP), dim3(32, 8)>>>(Wexp);
    routing_kernel<<<NTOK / 8, 256>>>(x, noise, Wr, br, gamma, beta);
    moe_gemm<<<dim3(DIM / NT, NTOK / MT, NEXP), 256, SMEM_BYTES>>>(bexp);
    combine_kernel<<<(NTOK * DIM / 4) / 256, 256>>>(out);
}

// round 13
// speedup vs baseline: 2.1041x; 1.0517x over previous
#include <cuda_runtime.h>
#include <cuda_fp16.h>
#include <cstdint>

// Problem constants
#define NTOK   8192      // B*S
#define DIM    1024
#define NEXP   8
#define LN_EPS 1e-5f

// GEMM tiling (fp16 mma.sync m16n8k16 + ldmatrix)
#define MT 128
#define NT 128
#define KT 32
#define NSTAGE 4
#define ASTR 40    // padded halfs per A row -> 80B stride (conflict-free LDSM)
#define BSTR 40

#define SMEM_BYTES (NSTAGE*MT*ASTR*2 + NSTAGE*NT*BSTR*2 + MT*4 + MT*4)

// ---------------- scratch (device globals; no allocation allowed) -----------
__device__ int    d_cnt[NEXP];
__device__ int    d_tok[NEXP * NTOK];       // packed tok*2 + slot
__device__ float  d_wt [NEXP * NTOK];
__device__ __half d_xh [NTOK * DIM];        // x fp16 (emitted by routing)
__device__ __half d_wh [NEXP * DIM * DIM];  // W_exp transposed [e][n][k] fp16
__device__ float  d_scr[2 * NTOK * DIM];    // per-slot expert outputs

// ---------------- helpers ---------------------------------------------------
__device__ __forceinline__ void mma_f16(float c[4], const uint32_t a[4], const uint32_t b[2]) {
    asm volatile(
        "mma.sync.aligned.m16n8k16.row.col.f32.f16.f16.f32 "
        "{%0,%1,%2,%3}, {%4,%5,%6,%7}, {%8,%9}, {%0,%1,%2,%3};\n"
        : "+f"(c[0]), "+f"(c[1]), "+f"(c[2]), "+f"(c[3])
        : "r"(a[0]), "r"(a[1]), "r"(a[2]), "r"(a[3]),
          "r"(b[0]), "r"(b[1]));
}
__device__ __forceinline__ void ldsm_x4(uint32_t& r0, uint32_t& r1, uint32_t& r2, uint32_t& r3,
                                        uint32_t addr) {
    asm volatile("ldmatrix.sync.aligned.m8n8.x4.shared.b16 {%0,%1,%2,%3}, [%4];"
                 : "=r"(r0), "=r"(r1), "=r"(r2), "=r"(r3) : "r"(addr));
}
__device__ __forceinline__ void cp16(uint32_t dst, const void* src) {
    asm volatile("cp.async.cg.shared.global [%0], [%1], 16;" :: "r"(dst), "l"(src));
}
__device__ __forceinline__ void cp_commit() { asm volatile("cp.async.commit_group;"); }
__device__ __forceinline__ void cp_wait2()  { asm volatile("cp.async.wait_group 2;"); }

// ---------------- kernel: init counters --------------------------------------
__global__ void init_kernel() {
    if (threadIdx.x < NEXP) d_cnt[threadIdx.x] = 0;
}

// ---------------- kernel: convert + transpose W_exp -> fp16 [e][n][k] --------
__global__ void convert_w(const float* __restrict__ W) {
    __shared__ __half t[32][33];
    int e  = blockIdx.z;
    int n0 = blockIdx.x * 32;
    int k0 = blockIdx.y * 32;
    int tx = threadIdx.x, ty = threadIdx.y;   // 32 x 8
    #pragma unroll
    for (int j = 0; j < 32; j += 8)
        t[ty + j][tx] = __float2half(W[((size_t)e * DIM + k0 + ty + j) * DIM + n0 + tx]);
    __syncthreads();
    #pragma unroll
    for (int j = 0; j < 32; j += 8)
        d_wh[((size_t)e * DIM + n0 + ty + j) * DIM + k0 + tx] = t[tx][ty + j];
}

// ---------------- kernel: routing (+ fp16 x emit) -----------------------------
__global__ __launch_bounds__(256) void routing_kernel(const float* __restrict__ x,
                                                      const float* __restrict__ noise,
                                                      const float* __restrict__ Wr,
                                                      const float* __restrict__ br,
                                                      const float* __restrict__ gamma,
                                                      const float* __restrict__ beta) {
    __shared__ float sW[8][1024];
    const int tid  = threadIdx.x;
    const int warp = tid >> 5;
    const int lane = tid & 31;

    const float4* w4 = (const float4*)Wr;
    for (int j = tid; j < 2048; j += 256) {
        float4 v = w4[j];
        int idx = j * 4;
        int d  = idx >> 3;
        int e0 = idx & 7;
        sW[e0 + 0][d] = v.x;
        sW[e0 + 1][d] = v.y;
        sW[e0 + 2][d] = v.z;
        sW[e0 + 3][d] = v.w;
    }
    __syncthreads();

    const int t = blockIdx.x * 8 + warp;
    const float4* xr = (const float4*)(x + (size_t)t * DIM);
    __half* xh = d_xh + (size_t)t * DIM;

    float acc[8] = {0.f,0.f,0.f,0.f,0.f,0.f,0.f,0.f};
    #pragma unroll
    for (int i = 0; i < 8; i++) {
        float4 xv = xr[i * 32 + lane];
        int d = i * 128 + lane * 4;
        #pragma unroll
        for (int e = 0; e < 8; e++) {
            float4 wv = *(const float4*)&sW[e][d];
            acc[e] += xv.x * wv.x + xv.y * wv.y + xv.z * wv.z + xv.w * wv.w;
        }
        __half2 h0 = __floats2half2_rn(xv.x, xv.y);
        __half2 h1 = __floats2half2_rn(xv.z, xv.w);
        *(__half2*)&xh[d + 0] = h0;
        *(__half2*)&xh[d + 2] = h1;
    }
    #pragma unroll
    for (int off = 16; off; off >>= 1) {
        #pragma unroll
        for (int e = 0; e < 8; e++)
            acc[e] += __shfl_down_sync(0xffffffffu, acc[e], off);
    }

    if (lane == 0) {
        float l[8];
        float mu = 0.f;
        #pragma unroll
        for (int e = 0; e < 8; e++) { l[e] = acc[e] + br[e]; mu += l[e]; }
        mu *= (1.f / 8.f);
        float var = 0.f;
        #pragma unroll
        for (int e = 0; e < 8; e++) { float d = l[e] - mu; var += d * d; }
        var *= (1.f / 8.f);
        float rstd = rsqrtf(var + LN_EPS);
        float mx = -1e30f;
        #pragma unroll
        for (int e = 0; e < 8; e++) {
            l[e] = (l[e] - mu) * rstd * gamma[e] + beta[e];
            mx = fmaxf(mx, l[e]);
        }
        float s = 0.f, p[8];
        #pragma unroll
        for (int e = 0; e < 8; e++) { p[e] = expf(l[e] - mx); s += p[e]; }
        float inv = 1.f / s;
        float r[8];
        #pragma unroll
        for (int e = 0; e < 8; e++) r[e] = p[e] * inv + noise[t * 8 + e];

        int i0 = 0; float v0 = r[0];
        #pragma unroll
        for (int e = 1; e < 8; e++) if (r[e] > v0) { v0 = r[e]; i0 = e; }
        int i1 = -1; float v1 = -1e30f;
        #pragma unroll
        for (int e = 0; e < 8; e++) if (e != i0 && r[e] > v1) { v1 = r[e]; i1 = e; }

        float e1 = expf(v1 - v0);
        float w0 = 1.f / (1.f + e1);
        float w1 = e1 / (1.f + e1);

        int p0 = atomicAdd(&d_cnt[i0], 1);
        d_tok[i0 * NTOK + p0] = t * 2 + 0; d_wt[i0 * NTOK + p0] = w0;
        int p1 = atomicAdd(&d_cnt[i1], 1);
        d_tok[i1 * NTOK + p1] = t * 2 + 1; d_wt[i1 * NTOK + p1] = w1;
    }
}

// ---------------- kernel: grouped expert GEMM (fp16 mma + ldmatrix, 4-stage) --
// grid: (DIM/NT, NTOK/MT, NEXP), 256 threads
__global__ __launch_bounds__(256, 2) void moe_gemm(const float* __restrict__ bexp) {
    const int e     = blockIdx.z;
    const int mtile = blockIdx.y;
    const int ntile = blockIdx.x;
    const int cnt   = d_cnt[e];
    const int row0  = mtile * MT;
    if (row0 >= cnt) return;

    extern __shared__ char smem_raw[];
    __half* As  = (__half*)smem_raw;                      // [NSTAGE][MT][ASTR]
    __half* Bs  = As + NSTAGE * MT * ASTR;                // [NSTAGE][NT][BSTR]
    int*   stok = (int*)(Bs + NSTAGE * NT * BSTR);        // [MT]
    float* swt  = (float*)(stok + MT);                    // [MT]

    const int tid  = threadIdx.x;
    const int warp = tid >> 5;
    const int lane = tid & 31;
    const int wm   = warp & 1;   // M direction, 64 rows each
    const int wn   = warp >> 1;  // N direction, 32 cols each
    const int gid  = lane >> 2;
    const int tg   = lane & 3;
    const int n0   = ntile * NT;

    if (tid < MT) {
        int r = row0 + tid;
        bool ok = (r < cnt);
        stok[tid] = ok ? d_tok[e * NTOK + r] : -1;
        swt[tid]  = ok ? d_wt [e * NTOK + r] : 0.f;
    }
    __syncthreads();

    uint32_t as_base = (uint32_t)__cvta_generic_to_shared(As);
    uint32_t bs_base = (uint32_t)__cvta_generic_to_shared(Bs);

    // ldmatrix per-lane coordinates
    const int a_r = (lane & 7) + ((lane >> 3) & 1) * 8;  // row within m16 tile
    const int a_c = (lane >> 4) * 8;                     // col offset (0/8)
    const int b_r = (lane & 7) + ((lane >> 4) << 3);     // n-row within 16 (j2,j3 -> +8)
    const int b_c = ((lane >> 3) & 1) * 8;               // k offset (0/8)

    auto load_stage = [&](int s, int k0) {
        {
            int row = tid >> 1;
            int tok2 = stok[row];
            const __half* src = d_xh + (size_t)(tok2 >> 1) * DIM + k0;
            #pragma unroll
            for (int j = 0; j < 2; j++) {
                int c16 = (tid & 1) + j * 2;
                uint32_t dst = as_base + (uint32_t)(((s * MT + row) * ASTR + c16 * 8) * 2);
                if (tok2 >= 0) cp16(dst, src + c16 * 8);
                else asm volatile("st.shared.v4.b32 [%0], {%1,%1,%1,%1};" :: "r"(dst), "r"(0u));
            }
        }
        {
            int row = tid >> 1;
            const __half* src = d_wh + ((size_t)e * DIM + n0 + row) * DIM + k0;
            #pragma unroll
            for (int j = 0; j < 2; j++) {
                int c16 = (tid & 1) + j * 2;
                uint32_t dst = bs_base + (uint32_t)(((s * NT + row) * BSTR + c16 * 8) * 2);
                cp16(dst, src + c16 * 8);
            }
        }
    };

    float acc[4][4][4];
    #pragma unroll
    for (int mi = 0; mi < 4; mi++)
        #pragma unroll
        for (int ni = 0; ni < 4; ni++)
            #pragma unroll
            for (int q = 0; q < 4; q++) acc[mi][ni][q] = 0.f;

    // prologue: 3 stages in flight
    load_stage(0, 0);          cp_commit();
    load_stage(1, KT);         cp_commit();
    load_stage(2, 2 * KT);     cp_commit();

    const int NKT = DIM / KT;  // 32
    int cs = 0;
    for (int kt = 0; kt < NKT; kt++) {
        cp_wait2();            // oldest of the 3 in-flight groups done
        __syncthreads();

        int ls = cs + 3; if (ls >= NSTAGE) ls -= NSTAGE;
        if (kt + 3 < NKT) load_stage(ls, (kt + 3) * KT);
        cp_commit();

        uint32_t asl = as_base + (uint32_t)(cs * MT * ASTR * 2);
        uint32_t bsl = bs_base + (uint32_t)(cs * NT * BSTR * 2);
        #pragma unroll
        for (int kk = 0; kk < KT; kk += 16) {
            uint32_t a[4][4], b[4][2];
            #pragma unroll
            for (int mi = 0; mi < 4; mi++) {
                int rb = wm * 64 + mi * 16;
                uint32_t addr = asl + (uint32_t)(((rb + a_r) * ASTR + kk + a_c) * 2);
                ldsm_x4(a[mi][0], a[mi][1], a[mi][2], a[mi][3], addr);
            }
            #pragma unroll
            for (int p = 0; p < 2; p++) {
                int cb = wn * 32 + p * 16;
                uint32_t addr = bsl + (uint32_t)(((cb + b_r) * BSTR + kk + b_c) * 2);
                ldsm_x4(b[p*2][0], b[p*2][1], b[p*2+1][0], b[p*2+1][1], addr);
            }
            #pragma unroll
            for (int mi = 0; mi < 4; mi++)
                #pragma unroll
                for (int ni = 0; ni < 4; ni++)
                    mma_f16(acc[mi][ni], a[mi], b[ni]);
        }

        cs++; if (cs >= NSTAGE) cs = 0;
    }

    // epilogue: d_scr[slot][tok] = w * (acc + bias)   (pure STG, no atomics)
    #pragma unroll
    for (int mi = 0; mi < 4; mi++) {
        #pragma unroll
        for (int half = 0; half < 2; half++) {
            int r = wm * 64 + mi * 16 + half * 8 + gid;
            int tok2 = stok[r];
            if (tok2 < 0) continue;
            float w = swt[r];
            float* orow = d_scr + ((size_t)(tok2 & 1) * NTOK + (size_t)(tok2 >> 1)) * DIM;
            #pragma unroll
            for (int ni = 0; ni < 4; ni++) {
                int col = n0 + wn * 32 + ni * 8 + tg * 2;
                float2 bb = *(const float2*)&bexp[e * DIM + col];
                float2 v;
                v.x = w * (acc[mi][ni][half * 2 + 0] + bb.x);
                v.y = w * (acc[mi][ni][half * 2 + 1] + bb.y);
                *(float2*)&orow[col] = v;
            }
        }
    }
}

// ---------------- kernel: combine two slots ----------------------------------
__global__ void combine_kernel(float* __restrict__ out) {
    size_t i = (size_t)blockIdx.x * blockDim.x + threadIdx.x;
    const float4* s0 = (const float4*)d_scr;
    const float4* s1 = (const float4*)(d_scr + (size_t)NTOK * DIM);
    float4 a = s0[i], b = s1[i];
    ((float4*)out)[i] = make_float4(a.x + b.x, a.y + b.y, a.z + b.z, a.w + b.w);
}

// ---------------- launch ------------------------------------------------------
extern "C" void kernel_launch(void* const* d_in, const int* in_sizes, int n_in,
                              void* d_out, int out_size) {
    const float* x     = (const float*)d_in[0];
    const float* noise = (const float*)d_in[1];
    const float* Wr    = (const float*)d_in[2];
    const float* br    = (const float*)d_in[3];
    const float* gamma = (const float*)d_in[4];
    const float* beta  = (const float*)d_in[5];
    const float* Wexp  = (const float*)d_in[6];
    const float* bexp  = (const float*)d_in[7];
    float* out = (float*)d_out;

    cudaFuncSetAttribute(moe_gemm, cudaFuncAttributeMaxDynamicSharedMemorySize, SMEM_BYTES);

    init_kernel<<<1, 32>>>();
    convert_w<<<dim3(DIM / 32, DIM / 32, NEXP), dim3(32, 8)>>>(Wexp);
    routing_kernel<<<NTOK / 8, 256>>>(x, noise, Wr, br, gamma, beta);
    moe_gemm<<<dim3(DIM / NT, NTOK / MT, NEXP), 256, SMEM_BYTES>>>(bexp);
    combine_kernel<<<(NTOK * DIM / 4) / 256, 256>>>(out);
}

// round 14
// speedup vs baseline: 2.8751x; 1.3664x over previous
#include <cuda_runtime.h>
#include <cuda_fp16.h>
#include <cstdint>

// Problem constants
#define NTOK   8192      // B*S
#define DIM    1024
#define NEXP   8
#define LN_EPS 1e-5f

// GEMM tiling (fp16 mma.sync m16n8k16 + ldmatrix)
#define MT 128
#define NT 128
#define KT 64            // halfs per k-stage -> 128B of k per row
#define NSTAGE 3
#define ASTR 72          // padded halfs per A row -> 144B stride (9 x 16B, odd -> conflict-free LDSM)
#define BSTR 72

#define SMEM_BYTES (NSTAGE*MT*ASTR*2 + NSTAGE*NT*BSTR*2 + MT*4 + MT*4)

// ---------------- scratch (device globals; no allocation allowed) -----------
__device__ int    d_cnt[NEXP];
__device__ int    d_tok[NEXP * NTOK];       // token index
__device__ float  d_wt [NEXP * NTOK];
__device__ __half d_xh [NTOK * DIM];        // x fp16 (emitted by routing)
__device__ __half d_wh [NEXP * DIM * DIM];  // W_exp transposed [e][n][k] fp16

// ---------------- helpers ---------------------------------------------------
__device__ __forceinline__ void mma_f16(float c[4], const uint32_t a[4], const uint32_t b[2]) {
    asm volatile(
        "mma.sync.aligned.m16n8k16.row.col.f32.f16.f16.f32 "
        "{%0,%1,%2,%3}, {%4,%5,%6,%7}, {%8,%9}, {%0,%1,%2,%3};\n"
        : "+f"(c[0]), "+f"(c[1]), "+f"(c[2]), "+f"(c[3])
        : "r"(a[0]), "r"(a[1]), "r"(a[2]), "r"(a[3]),
          "r"(b[0]), "r"(b[1]));
}
__device__ __forceinline__ void ldsm_x4(uint32_t& r0, uint32_t& r1, uint32_t& r2, uint32_t& r3,
                                        uint32_t addr) {
    asm volatile("ldmatrix.sync.aligned.m8n8.x4.shared.b16 {%0,%1,%2,%3}, [%4];"
                 : "=r"(r0), "=r"(r1), "=r"(r2), "=r"(r3) : "r"(addr));
}
__device__ __forceinline__ void cp16(uint32_t dst, const void* src) {
    asm volatile("cp.async.cg.shared.global [%0], [%1], 16;" :: "r"(dst), "l"(src));
}
__device__ __forceinline__ void cp_commit() { asm volatile("cp.async.commit_group;"); }
__device__ __forceinline__ void cp_wait1()  { asm volatile("cp.async.wait_group 1;"); }
__device__ __forceinline__ void red_v2(float* p, float v0, float v1) {
    asm volatile("red.global.add.v2.f32 [%0], {%1, %2};" :: "l"(p), "f"(v0), "f"(v1) : "memory");
}

// ---------------- kernel 0: zero output + counters ---------------------------
__global__ void zero_kernel(float* __restrict__ out) {
    size_t i = (size_t)blockIdx.x * blockDim.x + threadIdx.x;
    ((float4*)out)[i] = make_float4(0.f, 0.f, 0.f, 0.f);
    if (blockIdx.x == 0 && threadIdx.x < NEXP) d_cnt[threadIdx.x] = 0;
}

// ---------------- kernel: convert + transpose W_exp -> fp16 [e][n][k] --------
__global__ void convert_w(const float* __restrict__ W) {
    __shared__ __half t[32][33];
    int e  = blockIdx.z;
    int n0 = blockIdx.x * 32;
    int k0 = blockIdx.y * 32;
    int tx = threadIdx.x, ty = threadIdx.y;   // 32 x 8
    #pragma unroll
    for (int j = 0; j < 32; j += 8)
        t[ty + j][tx] = __float2half(W[((size_t)e * DIM + k0 + ty + j) * DIM + n0 + tx]);
    __syncthreads();
    #pragma unroll
    for (int j = 0; j < 32; j += 8)
        d_wh[((size_t)e * DIM + n0 + ty + j) * DIM + k0 + tx] = t[tx][ty + j];
}

// ---------------- kernel: routing (+ fp16 x emit) -----------------------------
__global__ __launch_bounds__(256) void routing_kernel(const float* __restrict__ x,
                                                      const float* __restrict__ noise,
                                                      const float* __restrict__ Wr,
                                                      const float* __restrict__ br,
                                                      const float* __restrict__ gamma,
                                                      const float* __restrict__ beta) {
    __shared__ float sW[8][1024];
    const int tid  = threadIdx.x;
    const int warp = tid >> 5;
    const int lane = tid & 31;

    const float4* w4 = (const float4*)Wr;
    for (int j = tid; j < 2048; j += 256) {
        float4 v = w4[j];
        int idx = j * 4;
        int d  = idx >> 3;
        int e0 = idx & 7;
        sW[e0 + 0][d] = v.x;
        sW[e0 + 1][d] = v.y;
        sW[e0 + 2][d] = v.z;
        sW[e0 + 3][d] = v.w;
    }
    __syncthreads();

    const int t = blockIdx.x * 8 + warp;
    const float4* xr = (const float4*)(x + (size_t)t * DIM);
    __half* xh = d_xh + (size_t)t * DIM;

    float acc[8] = {0.f,0.f,0.f,0.f,0.f,0.f,0.f,0.f};
    #pragma unroll
    for (int i = 0; i < 8; i++) {
        float4 xv = xr[i * 32 + lane];
        int d = i * 128 + lane * 4;
        #pragma unroll
        for (int e = 0; e < 8; e++) {
            float4 wv = *(const float4*)&sW[e][d];
            acc[e] += xv.x * wv.x + xv.y * wv.y + xv.z * wv.z + xv.w * wv.w;
        }
        __half2 h0 = __floats2half2_rn(xv.x, xv.y);
        __half2 h1 = __floats2half2_rn(xv.z, xv.w);
        *(__half2*)&xh[d + 0] = h0;
        *(__half2*)&xh[d + 2] = h1;
    }
    #pragma unroll
    for (int off = 16; off; off >>= 1) {
        #pragma unroll
        for (int e = 0; e < 8; e++)
            acc[e] += __shfl_down_sync(0xffffffffu, acc[e], off);
    }

    if (lane == 0) {
        float l[8];
        float mu = 0.f;
        #pragma unroll
        for (int e = 0; e < 8; e++) { l[e] = acc[e] + br[e]; mu += l[e]; }
        mu *= (1.f / 8.f);
        float var = 0.f;
        #pragma unroll
        for (int e = 0; e < 8; e++) { float d = l[e] - mu; var += d * d; }
        var *= (1.f / 8.f);
        float rstd = rsqrtf(var + LN_EPS);
        float mx = -1e30f;
        #pragma unroll
        for (int e = 0; e < 8; e++) {
            l[e] = (l[e] - mu) * rstd * gamma[e] + beta[e];
            mx = fmaxf(mx, l[e]);
        }
        float s = 0.f, p[8];
        #pragma unroll
        for (int e = 0; e < 8; e++) { p[e] = expf(l[e] - mx); s += p[e]; }
        float inv = 1.f / s;
        float r[8];
        #pragma unroll
        for (int e = 0; e < 8; e++) r[e] = p[e] * inv + noise[t * 8 + e];

        int i0 = 0; float v0 = r[0];
        #pragma unroll
        for (int e = 1; e < 8; e++) if (r[e] > v0) { v0 = r[e]; i0 = e; }
        int i1 = -1; float v1 = -1e30f;
        #pragma unroll
        for (int e = 0; e < 8; e++) if (e != i0 && r[e] > v1) { v1 = r[e]; i1 = e; }

        float e1 = expf(v1 - v0);
        float w0 = 1.f / (1.f + e1);
        float w1 = e1 / (1.f + e1);

        int p0 = atomicAdd(&d_cnt[i0], 1);
        d_tok[i0 * NTOK + p0] = t; d_wt[i0 * NTOK + p0] = w0;
        int p1 = atomicAdd(&d_cnt[i1], 1);
        d_tok[i1 * NTOK + p1] = t; d_wt[i1 * NTOK + p1] = w1;
    }
}

// ---------------- kernel: grouped expert GEMM (fp16 mma + ldmatrix, KT=64 x3) -
// grid: (DIM/NT, NTOK/MT, NEXP), 256 threads
__global__ __launch_bounds__(256, 2) void moe_gemm(const float* __restrict__ bexp,
                                                   float* __restrict__ out) {
    const int e     = blockIdx.z;
    const int mtile = blockIdx.y;
    const int ntile = blockIdx.x;
    const int cnt   = d_cnt[e];
    const int row0  = mtile * MT;
    if (row0 >= cnt) return;

    extern __shared__ char smem_raw[];
    __half* As  = (__half*)smem_raw;                      // [NSTAGE][MT][ASTR]
    __half* Bs  = As + NSTAGE * MT * ASTR;                // [NSTAGE][NT][BSTR]
    int*   stok = (int*)(Bs + NSTAGE * NT * BSTR);        // [MT]
    float* swt  = (float*)(stok + MT);                    // [MT]

    const int tid  = threadIdx.x;
    const int warp = tid >> 5;
    const int lane = tid & 31;
    const int wm   = warp & 1;   // M direction, 64 rows each
    const int wn   = warp >> 1;  // N direction, 32 cols each
    const int gid  = lane >> 2;
    const int tg   = lane & 3;
    const int n0   = ntile * NT;

    if (tid < MT) {
        int r = row0 + tid;
        bool ok = (r < cnt);
        stok[tid] = ok ? d_tok[e * NTOK + r] : -1;
        swt[tid]  = ok ? d_wt [e * NTOK + r] : 0.f;
    }
    __syncthreads();

    uint32_t as_base = (uint32_t)__cvta_generic_to_shared(As);
    uint32_t bs_base = (uint32_t)__cvta_generic_to_shared(Bs);

    // ldmatrix per-lane coordinates
    const int a_r = (lane & 7) + ((lane >> 3) & 1) * 8;  // row within m16 tile
    const int a_c = (lane >> 4) * 8;                     // col offset (0/8)
    const int b_r = (lane & 7) + ((lane >> 4) << 3);     // n-row within 16
    const int b_c = ((lane >> 3) & 1) * 8;               // k offset (0/8)

    // per-stage loads: 1024 16B-chunks for A, 1024 for B; 4 each per thread
    auto load_stage = [&](int s, int k0) {
        #pragma unroll
        for (int j = 0; j < 4; j++) {
            int idx = tid + 256 * j;       // 0..1023
            int row = idx >> 3;            // 0..127
            int ch  = idx & 7;             // 0..7 (16B chunks of 128B k-row)
            int tok = stok[row];
            uint32_t dst = as_base + (uint32_t)(((s * MT + row) * ASTR + ch * 8) * 2);
            if (tok >= 0) cp16(dst, d_xh + (size_t)tok * DIM + k0 + ch * 8);
            else asm volatile("st.shared.v4.b32 [%0], {%1,%1,%1,%1};" :: "r"(dst), "r"(0u));
        }
        #pragma unroll
        for (int j = 0; j < 4; j++) {
            int idx = tid + 256 * j;
            int row = idx >> 3;
            int ch  = idx & 7;
            uint32_t dst = bs_base + (uint32_t)(((s * NT + row) * BSTR + ch * 8) * 2);
            cp16(dst, d_wh + ((size_t)e * DIM + n0 + row) * DIM + k0 + ch * 8);
        }
    };

    float acc[4][4][4];
    #pragma unroll
    for (int mi = 0; mi < 4; mi++)
        #pragma unroll
        for (int ni = 0; ni < 4; ni++)
            #pragma unroll
            for (int q = 0; q < 4; q++) acc[mi][ni][q] = 0.f;

    // prologue: 2 stages in flight
    load_stage(0, 0);      cp_commit();
    load_stage(1, KT);     cp_commit();

    const int NKT = DIM / KT;  // 16
    int cs = 0;
    for (int kt = 0; kt < NKT; kt++) {
        cp_wait1();            // stage kt complete
        __syncthreads();       // all warps done with stage kt-1 (same buffer as kt+2)

        int ls = cs + 2; if (ls >= NSTAGE) ls -= NSTAGE;
        if (kt + 2 < NKT) load_stage(ls, (kt + 2) * KT);
        cp_commit();

        uint32_t asl = as_base + (uint32_t)(cs * MT * ASTR * 2);
        uint32_t bsl = bs_base + (uint32_t)(cs * NT * BSTR * 2);
        #pragma unroll
        for (int kk = 0; kk < KT; kk += 16) {
            uint32_t a[4][4], b[4][2];
            #pragma unroll
            for (int mi = 0; mi < 4; mi++) {
                int rb = wm * 64 + mi * 16;
                uint32_t addr = asl + (uint32_t)(((rb + a_r) * ASTR + kk + a_c) * 2);
                ldsm_x4(a[mi][0], a[mi][1], a[mi][2], a[mi][3], addr);
            }
            #pragma unroll
            for (int p = 0; p < 2; p++) {
                int cb = wn * 32 + p * 16;
                uint32_t addr = bsl + (uint32_t)(((cb + b_r) * BSTR + kk + b_c) * 2);
                ldsm_x4(b[p*2][0], b[p*2][1], b[p*2+1][0], b[p*2+1][1], addr);
            }
            #pragma unroll
            for (int mi = 0; mi < 4; mi++)
                #pragma unroll
                for (int ni = 0; ni < 4; ni++)
                    mma_f16(acc[mi][ni], a[mi], b[ni]);
        }

        cs++; if (cs >= NSTAGE) cs = 0;
    }

    // epilogue: out[tok] += w * (acc + bias)  (fire-and-forget red.v2)
    #pragma unroll
    for (int mi = 0; mi < 4; mi++) {
        #pragma unroll
        for (int half = 0; half < 2; half++) {
            int r = wm * 64 + mi * 16 + half * 8 + gid;
            int tok = stok[r];
            if (tok < 0) continue;
            float w = swt[r];
            float* orow = out + (size_t)tok * DIM;
            #pragma unroll
            for (int ni = 0; ni < 4; ni++) {
                int col = n0 + wn * 32 + ni * 8 + tg * 2;
                float2 bb = *(const float2*)&bexp[e * DIM + col];
                float v0 = w * (acc[mi][ni][half * 2 + 0] + bb.x);
                float v1 = w * (acc[mi][ni][half * 2 + 1] + bb.y);
                red_v2(&orow[col], v0, v1);
            }
        }
    }
}

// ---------------- launch ------------------------------------------------------
extern "C" void kernel_launch(void* const* d_in, const int* in_sizes, int n_in,
                              void* d_out, int out_size) {
    const float* x     = (const float*)d_in[0];
    const float* noise = (const float*)d_in[1];
    const float* Wr    = (const float*)d_in[2];
    const float* br    = (const float*)d_in[3];
    const float* gamma = (const float*)d_in[4];
    const float* beta  = (const float*)d_in[5];
    const float* Wexp  = (const float*)d_in[6];
    const float* bexp  = (const float*)d_in[7];
    float* out = (float*)d_out;

    cudaFuncSetAttribute(moe_gemm, cudaFuncAttributeMaxDynamicSharedMemorySize, SMEM_BYTES);

    zero_kernel<<<(NTOK * DIM / 4) / 256, 256>>>(out);
    convert_w<<<dim3(DIM / 32, DIM / 32, NEXP), dim3(32, 8)>>>(Wexp);
    routing_kernel<<<NTOK / 8, 256>>>(x, noise, Wr, br, gamma, beta);
    moe_gemm<<<dim3(DIM / NT, NTOK / MT, NEXP), 256, SMEM_BYTES>>>(bexp, out);
}